// round 1
// baseline (speedup 1.0000x reference)
#include <cuda_runtime.h>

// Problem constants
#define BATCH 32
#define T     1024
#define DIN   512
#define DH    512
#define M     (BATCH * T)   // 32768 rows

// 64 MB scratch for X = inputs @ W^T + b   (allowed: __device__ global)
__device__ float g_X[(size_t)M * DH];

// ---------------------------------------------------------------------------
// GEMM: X[m, n] = sum_k A[m, k] * W[n, k] + b[n]
// A: (M, 512) row-major (inputs flattened over batch*time)
// W: (512, 512) row-major (n-major, k contiguous)
// 128x128 block tile, kTile = 8, 256 threads, 8x8 accumulator per thread.
// ---------------------------------------------------------------------------
__global__ __launch_bounds__(256, 2)
void gemm_kernel(const float* __restrict__ A,
                 const float* __restrict__ W,
                 const float* __restrict__ bias,
                 float* __restrict__ X)
{
    __shared__ float As[8][128];   // As[k][m]
    __shared__ float Bs[8][128];   // Bs[k][n]

    const int bm = blockIdx.x * 128;   // 256 blocks in M
    const int bn = blockIdx.y * 128;   // 4 blocks in N
    const int tid = threadIdx.x;
    const int tx = tid & 15;           // 0..15 -> n subtile
    const int ty = tid >> 4;           // 0..15 -> m subtile

    // load mapping: each thread loads one float4 of A and one float4 of W
    const int lr = tid >> 1;           // 0..127
    const int lc = (tid & 1) << 2;     // 0 or 4

    float acc[8][8];
#pragma unroll
    for (int i = 0; i < 8; i++)
#pragma unroll
        for (int j = 0; j < 8; j++) acc[i][j] = 0.0f;

    const float* aptr = A + (size_t)(bm + lr) * DIN + lc;
    const float* wptr = W + (size_t)(bn + lr) * DIN + lc;

    for (int k0 = 0; k0 < DIN; k0 += 8) {
        float4 av = *(const float4*)(aptr + k0);
        float4 wv = *(const float4*)(wptr + k0);
        __syncthreads();
        As[lc + 0][lr] = av.x;
        As[lc + 1][lr] = av.y;
        As[lc + 2][lr] = av.z;
        As[lc + 3][lr] = av.w;
        Bs[lc + 0][lr] = wv.x;
        Bs[lc + 1][lr] = wv.y;
        Bs[lc + 2][lr] = wv.z;
        Bs[lc + 3][lr] = wv.w;
        __syncthreads();

#pragma unroll
        for (int k = 0; k < 8; k++) {
            float a[8], bb[8];
#pragma unroll
            for (int i = 0; i < 8; i++) a[i]  = As[k][ty * 8 + i];
#pragma unroll
            for (int j = 0; j < 8; j++) bb[j] = Bs[k][tx * 8 + j];
#pragma unroll
            for (int i = 0; i < 8; i++)
#pragma unroll
                for (int j = 0; j < 8; j++)
                    acc[i][j] += a[i] * bb[j];
        }
    }

    // epilogue: add bias, store as float4
    float bv[8];
#pragma unroll
    for (int j = 0; j < 8; j++) bv[j] = bias[bn + tx * 8 + j];

#pragma unroll
    for (int i = 0; i < 8; i++) {
        float* out_row = X + (size_t)(bm + ty * 8 + i) * DH + bn + tx * 8;
        float4 v0, v1;
        v0.x = acc[i][0] + bv[0];
        v0.y = acc[i][1] + bv[1];
        v0.z = acc[i][2] + bv[2];
        v0.w = acc[i][3] + bv[3];
        v1.x = acc[i][4] + bv[4];
        v1.y = acc[i][5] + bv[5];
        v1.z = acc[i][6] + bv[6];
        v1.w = acc[i][7] + bv[7];
        *(float4*)(out_row + 0) = v0;
        *(float4*)(out_row + 4) = v1;
    }
}

// ---------------------------------------------------------------------------
// Scan: per (b, h) sequence, two-state linear recurrence + threshold.
//   s[t] = a*s[t-1] + X[t];  m[t] = a*m[t-1] + (1-a)*s[t];  out = (m > thr)
// 64 blocks x 256 threads: block = (b, half of H). Coalesced stride-DH loads.
// ---------------------------------------------------------------------------
__global__ __launch_bounds__(256)
void scan_kernel(const float* __restrict__ X,
                 const float* __restrict__ thr_p,
                 float* __restrict__ out)
{
    const int b = blockIdx.x >> 1;
    const int h = ((blockIdx.x & 1) << 8) + threadIdx.x;

    const float ALPHA = 0.36787944117144233f;   // exp(-1)
    const float OMB   = 1.0f - ALPHA;           // 1 - beta
    const float thr   = thr_p[0];

    const float* xp = X   + (size_t)b * T * DH + h;
    float*       op = out + (size_t)b * T * DH + h;

    float s = 0.0f, m = 0.0f;

    for (int t0 = 0; t0 < T; t0 += 8) {
        float x[8];
#pragma unroll
        for (int u = 0; u < 8; u++) x[u] = xp[(size_t)(t0 + u) * DH];
        float sp[8];
#pragma unroll
        for (int u = 0; u < 8; u++) {
            s = fmaf(ALPHA, s, x[u]);
            m = fmaf(ALPHA, m, OMB * s);
            sp[u] = (m > thr) ? 1.0f : 0.0f;
        }
#pragma unroll
        for (int u = 0; u < 8; u++) op[(size_t)(t0 + u) * DH] = sp[u];
    }
}

// ---------------------------------------------------------------------------
extern "C" void kernel_launch(void* const* d_in, const int* in_sizes, int n_in,
                              void* d_out, int out_size)
{
    const float* inputs = (const float*)d_in[0];  // (32, 1024, 512)
    const float* W      = (const float*)d_in[1];  // (512, 512)
    const float* bias   = (const float*)d_in[2];  // (512,)
    const float* thr    = (const float*)d_in[3];  // scalar
    float*       out    = (float*)d_out;          // (32, 1024, 512)

    float* Xs;
    cudaGetSymbolAddress((void**)&Xs, g_X);

    dim3 ggrid(M / 128, DH / 128);   // (256, 4)
    gemm_kernel<<<ggrid, 256>>>(inputs, W, bias, Xs);

    scan_kernel<<<BATCH * 2, 256>>>(Xs, thr, out);
}